// round 13
// baseline (speedup 1.0000x reference)
#include <cuda_runtime.h>
#include <cstdint>

#define En 64
#define An 8
#define Ln 2048
#define Dn 128
#define Hn 8
#define DKn 16
#define EA 512
#define SPLIT 4
#define RPS 512
#define TL 64

typedef unsigned long long ull;

__device__ __forceinline__ ull fma2(ull a, ull b, ull c) {
    ull d; asm("fma.rn.f32x2 %0, %1, %2, %3;" : "=l"(d) : "l"(a), "l"(b), "l"(c)); return d;
}
__device__ __forceinline__ ull mul2(ull a, ull b) {
    ull d; asm("mul.rn.f32x2 %0, %1, %2;" : "=l"(d) : "l"(a), "l"(b)); return d;
}
__device__ __forceinline__ ull pack2(float x, float y) {
    ull r; asm("mov.b64 %0, {%1,%2};" : "=l"(r) : "f"(x), "f"(y)); return r;
}
__device__ __forceinline__ float2 unpack2(ull v) {
    float2 r; asm("mov.b64 {%0,%1}, %2;" : "=f"(r.x), "=f"(r.y) : "l"(v)); return r;
}
__device__ __forceinline__ float ex2(float x) {
    float y; asm("ex2.approx.ftz.f32 %0, %1;" : "=f"(y) : "f"(x)); return y;
}

__device__ __align__(16) float g_Rk[EA * Hn * Dn];
__device__ __align__(16) float g_part[EA * SPLIT * 1040];  // m[8],Z[8],w[8][128]
__device__ int g_cnt[EA];

// ---------------- Kernel 1: fused query pipeline -> Rk ----------------
__global__ void prep(const float* __restrict__ gc, const float* __restrict__ dep,
                     const float* __restrict__ tbd, const float* __restrict__ loadv,
                     const float* __restrict__ Wqp, const float* __restrict__ Wq,
                     const float* __restrict__ Wk, const float* __restrict__ Wkp) {
    __shared__ float qsm[Dn];
    __shared__ float qhs[Hn * DKn];
    __shared__ float ut[Hn * 132];
    int b = blockIdx.x, e = b >> 3, a = b & 7, t = threadIdx.x;  // 256 threads

    if (t < Dn) {  // q[t]: 3 interleaved chains
        const float* s0 = gc + e * Dn;
        const float* s1 = dep + e * Dn;
        const float* s2 = tbd + e * Dn;
        float a0 = loadv[e * An + a] * Wqp[384 * Dn + t];
        float a1 = (float)a * Wqp[385 * Dn + t];
        float a2 = 0.f;
#pragma unroll 4
        for (int i = 0; i < Dn; i++) {
            a0 += s0[i] * Wqp[i * Dn + t];
            a1 += s1[i] * Wqp[(Dn + i) * Dn + t];
            a2 += s2[i] * Wqp[(2 * Dn + i) * Dn + t];
        }
        qsm[t] = (a0 + a1) + a2;
    }
    __syncthreads();
    if (t < Dn) {  // qh[h][k]
        int h = t >> 4, k = t & 15;
        float acc = 0.f;
#pragma unroll 4
        for (int d = 0; d < Dn; d++) acc += qsm[d] * Wq[(h * Dn + d) * DKn + k];
        qhs[t] = acc;
    }
    __syncthreads();
    if (t < Dn) {  // u[h][d=t], scale folded
        const float SC = 0.25f * 1.4426950408889634f;
#pragma unroll
        for (int h = 0; h < Hn; h++) {
            const float* wkr = Wk + (h * Dn + t) * DKn;
            const float* qh = qhs + h * DKn;
            float acc = 0.f;
#pragma unroll
            for (int k = 0; k < DKn; k++) acc += qh[k] * wkr[k];
            ut[h * 132 + t] = SC * acc;
        }
    }
    __syncthreads();
    {  // Rk[h][i] = sum_d Wkp[i][d]*u[h][d]; thread (i=t>>1, half=t&1)
        int i = t >> 1, half = t & 1;
        const float* wrow = Wkp + i * Dn + 64 * half;
        float acc[Hn];
#pragma unroll
        for (int h = 0; h < Hn; h++) acc[h] = 0.f;
#pragma unroll
        for (int p = 0; p < 4; p++) {
            float4 v0 = *(const float4*)(wrow + 16 * p);
            float4 v1 = *(const float4*)(wrow + 16 * p + 4);
            float4 v2 = *(const float4*)(wrow + 16 * p + 8);
            float4 v3 = *(const float4*)(wrow + 16 * p + 12);
#pragma unroll
            for (int h = 0; h < Hn; h++) {
                const float* u = ut + h * 132 + 64 * half + 16 * p;
                acc[h] += v0.x*u[0] + v0.y*u[1] + v0.z*u[2] + v0.w*u[3]
                        + v1.x*u[4] + v1.y*u[5] + v1.z*u[6] + v1.w*u[7]
                        + v2.x*u[8] + v2.y*u[9] + v2.z*u[10] + v2.w*u[11]
                        + v3.x*u[12] + v3.y*u[13] + v3.z*u[14] + v3.w*u[15];
            }
        }
#pragma unroll
        for (int h = 0; h < Hn; h++) acc[h] += __shfl_xor_sync(0xffffffffu, acc[h], 1);
        if (!half)
#pragma unroll
            for (int h = 0; h < Hn; h++) g_Rk[((size_t)b * Hn + h) * Dn + i] = acc[h];
    }
}

// ---------------- Kernel 2: main, 512 thr, warp-pair (stripe, head-half) ----------------
// smem floats: [0,16384) 8 stripes x 2 bufs x 8 rows x 128 | pd 16 warps x 64 @16384
//              sMZ 16 warps x 8 @17408 | total 17536 floats (70.1KB)
#define SM_PD 16384
#define SM_MZ 17408
#define SMEM_BYTES (17536 * 4)

__global__ __launch_bounds__(512, 2)
void decoder_main(const float* __restrict__ emb, const int* __restrict__ lens,
                  const float* __restrict__ Wvp, const float* __restrict__ Wv,
                  const float* __restrict__ Wo, float* __restrict__ out) {
    extern __shared__ float sm[];
    __shared__ int sflag;

    int blk = blockIdx.x, b = blk >> 2, sp = blk & 3, t = threadIdx.x;
    int wrp = t >> 5, lane = t & 31;
    int s8 = wrp >> 1, hh = wrp & 1;          // stripe, head-half
    int h4 = lane & 3, q = lane >> 2;         // head-in-half, d-chunk (16 floats)
    int H = hh * 4 + h4;
    int len = lens[b];
    int cnt = min(len - sp * RPS, RPS);
    int ntiles = (cnt > 0) ? ((cnt + TL - 1) >> 6) : 0;
    const float* embp = emb + (size_t)b * (Ln * Dn) + (size_t)sp * RPS * Dn;

    float* wbuf = sm + s8 * 2048;             // 2 bufs x 8 rows x 128
    float* pd   = sm + SM_PD + wrp * 64;      // [8 rows][4 h float2]
    float* sMZ  = sm + SM_MZ;
    uint32_t wdst = (uint32_t)__cvta_generic_to_shared(wbuf) + (uint32_t)lane * 16;

    // Rk: lane (h4,q) holds floats 16q..16q+15 of head H
    ull rk[8];
    {
        const ulonglong2* rb = (const ulonglong2*)(g_Rk + ((size_t)b * Hn + H) * Dn + 16 * q);
#pragma unroll
        for (int j = 0; j < 4; j++) { ulonglong2 v = rb[j]; rk[2 * j] = v.x; rk[2 * j + 1] = v.y; }
    }

    float m = -30000.f, Z = 0.f;
    ull w0[4], w1[4];
#pragma unroll
    for (int i = 0; i < 4; i++) { w0[i] = 0ull; w1[i] = 0ull; }

#define LD_STRIPE(tt, bufk)                                                              \
    do {                                                                                  \
        const float* _s = embp + (size_t)((tt) * TL + s8 * 8) * Dn + lane * 4;            \
        uint32_t _d = wdst + (uint32_t)(bufk) * 4096;                                     \
        _Pragma("unroll")                                                                 \
        for (int _i = 0; _i < 8; _i++)                                                    \
            asm volatile("cp.async.cg.shared.global [%0], [%1], 16;\n"                    \
                         :: "r"(_d + _i * 512), "l"(_s + _i * Dn) : "memory");            \
        asm volatile("cp.async.commit_group;\n" ::: "memory");                            \
    } while (0)
#define PAIR_BAR() asm volatile("bar.sync %0, 64;" :: "r"(s8 + 8) : "memory")

    if (ntiles > 0) {
        if (hh == 0) {
            LD_STRIPE(0, 0);
            if (ntiles > 1) LD_STRIPE(1, 1);
        }
        for (int tt = 0; tt < ntiles; tt++) {
            if (hh == 0) {
                if (tt + 1 < ntiles) asm volatile("cp.async.wait_group 1;\n" ::: "memory");
                else                 asm volatile("cp.async.wait_group 0;\n" ::: "memory");
            }
            PAIR_BAR();
            const float* tb = wbuf + (tt & 1) * 1024;
            int base = tt * TL + s8 * 8;

            // score: 8 rows; lane (h4,q) covers 16 floats; reduce over q via 3 shfls
            float sp8[8];
#pragma unroll
            for (int i = 0; i < 8; i++) {
                const ulonglong2* rp = (const ulonglong2*)(tb + i * Dn + 16 * q);
                ull a0 = 0ull, a1 = 0ull;
#pragma unroll
                for (int j = 0; j < 4; j++) {
                    ulonglong2 ev = rp[j];
                    a0 = fma2(ev.x, rk[2 * j], a0);
                    a1 = fma2(ev.y, rk[2 * j + 1], a1);
                }
                float2 fa = unpack2(a0), fb = unpack2(a1);
                float sv = (fa.x + fa.y) + (fb.x + fb.y);
                sv += __shfl_xor_sync(0xffffffffu, sv, 4);
                sv += __shfl_xor_sync(0xffffffffu, sv, 8);
                sv += __shfl_xor_sync(0xffffffffu, sv, 16);
                sp8[i] = (base + i < cnt) ? sv : -1e30f;
            }

            // per-warp online softmax for head H (state dup over q)
            float tm = sp8[0];
#pragma unroll
            for (int i = 1; i < 8; i++) tm = fmaxf(tm, sp8[i]);
            float mn = fmaxf(m, tm);
            float f = ex2(m - mn);
            m = mn;
            float zs = 0.f;
#pragma unroll
            for (int i = 0; i < 8; i++) {
                sp8[i] = (sp8[i] > -1e29f) ? ex2(sp8[i] - mn) : 0.f;
                zs += sp8[i];
            }
            Z = Z * f + zs;

            // stash p: lane (h4,q) writes row q, head h4 (duplicated float2)
            *(float2*)(pd + q * 8 + 2 * h4) = make_float2(sp8[q], sp8[q]);
            __syncwarp();

            // rescale + accumulate (lane = dq covers floats 4*lane..+3)
#pragma unroll
            for (int i = 0; i < 4; i++) {
                float fh = __shfl_sync(0xffffffffu, f, i);
                ull fp = pack2(fh, fh);
                w0[i] = mul2(w0[i], fp);
                w1[i] = mul2(w1[i], fp);
            }
#pragma unroll
            for (int i = 0; i < 8; i++) {
                ulonglong2 ev = *(const ulonglong2*)(tb + i * Dn + 4 * lane);
                const ull* pdr = (const ull*)(pd + i * 8);
#pragma unroll
                for (int j = 0; j < 4; j++) {
                    w0[j] = fma2(pdr[j], ev.x, w0[j]);
                    w1[j] = fma2(pdr[j], ev.y, w1[j]);
                }
            }
            PAIR_BAR();
            if (hh == 0 && tt + 2 < ntiles) LD_STRIPE(tt + 2, tt & 1);
        }
    }

    // ---- CTA merge of 16 warp partials ----
    if (q == 0) { sMZ[wrp * 8 + h4] = m; sMZ[wrp * 8 + 4 + h4] = Z; }
    __syncthreads();
    {
        ulonglong2* Wm = (ulonglong2*)sm;  // [16 warps][4 h][32 lanes] x 16B = 32KB
#pragma unroll
        for (int j = 0; j < 4; j++) {
            ulonglong2 v; v.x = w0[j]; v.y = w1[j];
            Wm[(wrp * 4 + j) * 32 + lane] = v;
        }
    }
    __syncthreads();
    {
        int h2 = t & 7, dq = t >> 3;             // head, d-pair (0..63)
        int hh2 = h2 >> 2, h42 = h2 & 3;
        float mc = -30000.f;
#pragma unroll
        for (int s = 0; s < 8; s++) mc = fmaxf(mc, sMZ[(s * 2 + hh2) * 8 + h42]);
        float Zc = 0.f;
        float2 acc = make_float2(0.f, 0.f);
        const float2* Wmf = (const float2*)sm;   // [16][4][64] float2
#pragma unroll
        for (int s = 0; s < 8; s++) {
            int wv = s * 2 + hh2;
            float fw = ex2(sMZ[wv * 8 + h42] - mc);
            Zc += sMZ[wv * 8 + 4 + h42] * fw;
            float2 v = Wmf[(wv * 4 + h42) * 64 + dq];
            acc.x += fw * v.x; acc.y += fw * v.y;
        }
        float* gp = g_part + (size_t)blk * 1040;
        *(float2*)(gp + 16 + h2 * Dn + 2 * dq) = acc;
        if (dq == 0) { gp[h2] = mc; gp[8 + h2] = Zc; }
    }
    __syncthreads();

    // ---- last-arriver combine + epilogue ----
    __threadfence();
    if (t == 0) {
        int r = atomicAdd(&g_cnt[b], 1);
        sflag = (r == SPLIT - 1);
        if (r == SPLIT - 1) g_cnt[b] = 0;
    }
    __syncthreads();
    if (!sflag) return;
    __threadfence();

    int a = b & 7;
    float* cc   = sm;
    float* wfs  = sm + 32;
    float* vmid = sm + 32 + Hn * Dn;
    float* sCtx = vmid + Hn * Dn;
    const float* P0 = g_part + (size_t)(b * SPLIT) * 1040;
    const float* P1 = P0 + 1040;
    const float* P2 = P1 + 1040;
    const float* P3 = P2 + 1040;

    if (t < 8) {
        float m0 = P0[t], m1 = P1[t], m2 = P2[t], m3 = P3[t];
        float mm = fmaxf(fmaxf(m0, m1), fmaxf(m2, m3));
        float a0 = ex2(m0 - mm), a1 = ex2(m1 - mm), a2 = ex2(m2 - mm), a3 = ex2(m3 - mm);
        float inv = 1.f / (P0[8 + t] * a0 + P1[8 + t] * a1 + P2[8 + t] * a2 + P3[8 + t] * a3);
        cc[t] = a0 * inv; cc[8 + t] = a1 * inv; cc[16 + t] = a2 * inv; cc[24 + t] = a3 * inv;
    }
    __syncthreads();
    if (t < 128) {
#pragma unroll
        for (int hh2 = 0; hh2 < Hn; hh2++) {
            int off = 16 + hh2 * Dn + t;
            wfs[hh2 * Dn + t] = P0[off] * cc[hh2] + P1[off] * cc[8 + hh2]
                              + P2[off] * cc[16 + hh2] + P3[off] * cc[24 + hh2];
        }
    }
    __syncthreads();
    if (t < 128) {  // vmid[h][t] = wfs[h] @ Wvp + a*Wvp[128]
        float acc[Hn];
        float bias = (float)a * Wvp[Dn * Dn + t];
#pragma unroll
        for (int hh2 = 0; hh2 < Hn; hh2++) acc[hh2] = bias;
#pragma unroll 4
        for (int i = 0; i < Dn; i++) {
            float wv = Wvp[i * Dn + t];
#pragma unroll
            for (int hh2 = 0; hh2 < Hn; hh2++) acc[hh2] += wfs[hh2 * Dn + i] * wv;
        }
#pragma unroll
        for (int hh2 = 0; hh2 < Hn; hh2++) vmid[hh2 * Dn + t] = acc[hh2];
    }
    __syncthreads();
    if (t < 128) {  // ctx[h][k]
        int hh2 = t >> 4, k = t & 15;
        const float* wvr = Wv + hh2 * Dn * DKn + k;
        const float* vm = vmid + hh2 * Dn;
        float acc = 0.f;
#pragma unroll 4
        for (int d = 0; d < Dn; d++) acc += vm[d] * wvr[d * DKn];
        sCtx[t] = acc;
    }
    __syncthreads();
    if (t < 128) {  // out = ctx @ Wo
        float acc = 0.f;
#pragma unroll 4
        for (int j = 0; j < Hn * DKn; j++) acc += sCtx[j] * Wo[j * Dn + t];
        out[(size_t)b * Dn + t] = acc;
    }
}

// ---------------------------------------------------------------------------
extern "C" void kernel_launch(void* const* d_in, const int* in_sizes, int n_in,
                              void* d_out, int out_size) {
    const float* gc      = (const float*)d_in[0];
    const float* depot   = (const float*)d_in[1];
    const float* tbd     = (const float*)d_in[2];
    const float* loadv   = (const float*)d_in[3];
    const float* emb     = (const float*)d_in[4];
    const int*   lens    = (const int*)  d_in[5];
    const float* Wq_proj = (const float*)d_in[6];
    const float* Wk_proj = (const float*)d_in[7];
    const float* Wv_proj = (const float*)d_in[8];
    const float* Wq      = (const float*)d_in[9];
    const float* Wk      = (const float*)d_in[10];
    const float* Wv      = (const float*)d_in[11];
    const float* Wo      = (const float*)d_in[12];
    float* out = (float*)d_out;

    prep<<<EA, 256>>>(gc, depot, tbd, loadv, Wq_proj, Wq, Wk, Wk_proj);

    cudaFuncSetAttribute(decoder_main, cudaFuncAttributeMaxDynamicSharedMemorySize, SMEM_BYTES);
    decoder_main<<<EA * SPLIT, 512, SMEM_BYTES>>>(emb, lens, Wv_proj, Wv, Wo, out);
}